// round 1
// baseline (speedup 1.0000x reference)
#include <cuda_runtime.h>

#define N_NODES 100000
#define NPAD    100032          // padded node count for transposed features (mult of 32, fp4-aligned)
#define N_EDGES 1600000
#define N_DIV   9
#define IN_F    128
#define OUT_F   64
#define OUT_TOT (N_DIV * OUT_F) // 576

// Scratch (device globals: allocation-free per harness rules)
__device__ float g_Wh[(size_t)N_DIV * N_NODES * OUT_F];  // 230.4 MB: per-division projected+norm-scaled features
__device__ float g_featT[(size_t)IN_F * NPAD];           // 51.2 MB: feature transposed [f][n]
__device__ float g_Wt[N_DIV * IN_F * OUT_F];             // 288 KB: W transposed [d][f][o]

// ---------------------------------------------------------------------------
// Kernel 0: transpose W [d][o][f] -> Wt [d][f][o]  (tiny, one-time per launch)
// ---------------------------------------------------------------------------
__global__ void k_transpose_W(const float* __restrict__ W) {
    int t = blockIdx.x * blockDim.x + threadIdx.x;
    if (t >= N_DIV * IN_F * OUT_F) return;
    int o = t & (OUT_F - 1);
    int f = (t >> 6) & (IN_F - 1);
    int d = t >> 13;
    g_Wt[t] = W[d * IN_F * OUT_F + o * IN_F + f];
}

// ---------------------------------------------------------------------------
// Kernel 1: transpose feature [n][f] -> featT [f][n]  (32x32 smem tiles)
// Zero-fills the NPAD tail so the GEMM needs no bounds checks on loads.
// ---------------------------------------------------------------------------
__global__ void k_transpose_feat(const float* __restrict__ feat) {
    __shared__ float tile[32][33];
    int n0 = blockIdx.x * 32;
    int f0 = blockIdx.y * 32;
    int x = threadIdx.x, y = threadIdx.y;  // 32 x 8
#pragma unroll
    for (int j = 0; j < 32; j += 8) {
        int n = n0 + y + j;
        tile[y + j][x] = (n < N_NODES) ? feat[(size_t)n * IN_F + f0 + x] : 0.f;
    }
    __syncthreads();
#pragma unroll
    for (int j = 0; j < 32; j += 8) {
        g_featT[(size_t)(f0 + y + j) * NPAD + n0 + x] = tile[x][y + j];
    }
}

// ---------------------------------------------------------------------------
// Kernel 2: zero d_out (accumulator target for the edge scatter)
// ---------------------------------------------------------------------------
__global__ void k_zero(float4* __restrict__ out, int n4) {
    int i = blockIdx.x * blockDim.x + threadIdx.x;
    if (i < n4) out[i] = make_float4(0.f, 0.f, 0.f, 0.f);
}

// ---------------------------------------------------------------------------
// Kernel 3: GEMM  Wh[d][n][o] = (featT[:,n] . Wt[d][:,o]) * norm[n]
// Tile: 64 nodes x 64 outputs (one division) per block, K=128 resident.
// Both operands K-major-transposed in smem -> clean float4 LDS, zero conflicts.
// Inner loop uses packed fp32x2 FMA (FFMA2): exact fp32, 2 MACs/inst.
// ---------------------------------------------------------------------------
__global__ __launch_bounds__(256) void k_gemm(const float* __restrict__ norm) {
    extern __shared__ float sh[];
    float* AsT = sh;               // [128][64]  AsT[k][m] = featT[k][n0+m]
    float* BsT = sh + IN_F * 64;   // [128][64]  BsT[k][o] = Wt[d][k][o]

    const int d   = blockIdx.y;
    const int n0  = blockIdx.x * 64;
    const int tid = threadIdx.x;

#pragma unroll
    for (int it = 0; it < 8; it++) {
        int idx = tid + it * 256;              // 0..2047 float4 units
        int k = idx >> 4, c = idx & 15;
        *(float4*)(AsT + k * 64 + c * 4) =
            *(const float4*)(g_featT + (size_t)k * NPAD + n0 + c * 4);
        *(float4*)(BsT + idx * 4) =
            *(const float4*)(g_Wt + d * (IN_F * OUT_F) + idx * 4);
    }
    __syncthreads();

    const int tx = tid & 15;       // output quad: cols tx*4 .. tx*4+3
    const int ty = tid >> 4;       // node quad:   rows ty*4 .. ty*4+3

    unsigned long long acc[4][2] = {};  // acc[row][pair] : f32x2 packed accumulators

#pragma unroll 8
    for (int k = 0; k < IN_F; k++) {
        float4 a = ((const float4*)AsT)[k * 16 + ty];       // 4 node rows at this k
        ulonglong2 b = ((const ulonglong2*)BsT)[k * 16 + tx]; // 4 output cols as 2 f32x2

        unsigned long long aa;
        asm("mov.b64 %0, {%1, %1};" : "=l"(aa) : "f"(a.x));
        asm("fma.rn.f32x2 %0, %1, %2, %0;" : "+l"(acc[0][0]) : "l"(aa), "l"(b.x));
        asm("fma.rn.f32x2 %0, %1, %2, %0;" : "+l"(acc[0][1]) : "l"(aa), "l"(b.y));
        asm("mov.b64 %0, {%1, %1};" : "=l"(aa) : "f"(a.y));
        asm("fma.rn.f32x2 %0, %1, %2, %0;" : "+l"(acc[1][0]) : "l"(aa), "l"(b.x));
        asm("fma.rn.f32x2 %0, %1, %2, %0;" : "+l"(acc[1][1]) : "l"(aa), "l"(b.y));
        asm("mov.b64 %0, {%1, %1};" : "=l"(aa) : "f"(a.z));
        asm("fma.rn.f32x2 %0, %1, %2, %0;" : "+l"(acc[2][0]) : "l"(aa), "l"(b.x));
        asm("fma.rn.f32x2 %0, %1, %2, %0;" : "+l"(acc[2][1]) : "l"(aa), "l"(b.y));
        asm("mov.b64 %0, {%1, %1};" : "=l"(aa) : "f"(a.w));
        asm("fma.rn.f32x2 %0, %1, %2, %0;" : "+l"(acc[3][0]) : "l"(aa), "l"(b.x));
        asm("fma.rn.f32x2 %0, %1, %2, %0;" : "+l"(acc[3][1]) : "l"(aa), "l"(b.y));
    }

#pragma unroll
    for (int i = 0; i < 4; i++) {
        int n = n0 + ty * 4 + i;
        if (n >= N_NODES) continue;
        float s = norm[n];
        float x0, x1, x2, x3;
        asm("mov.b64 {%0, %1}, %2;" : "=f"(x0), "=f"(x1) : "l"(acc[i][0]));
        asm("mov.b64 {%0, %1}, %2;" : "=f"(x2), "=f"(x3) : "l"(acc[i][1]));
        float4 v = make_float4(x0 * s, x1 * s, x2 * s, x3 * s);
        *(float4*)(g_Wh + ((size_t)d * N_NODES + n) * OUT_F + tx * 4) = v;
    }
}

// ---------------------------------------------------------------------------
// Kernel 4: edge scatter. 16 threads per edge; each handles one float4 (16B)
// of the 256B message row. Vectorized no-return atomic (red.global.add.v4.f32).
// ---------------------------------------------------------------------------
__global__ __launch_bounds__(256) void k_scatter(const int* __restrict__ src,
                                                 const int* __restrict__ dst,
                                                 const int* __restrict__ ediv,
                                                 float* __restrict__ out) {
    int t = blockIdx.x * blockDim.x + threadIdx.x;
    int e = t >> 4;
    if (e >= N_EDGES) return;
    int c  = t & 15;
    int s  = __ldg(src + e);
    int dd = __ldg(dst + e);
    int dv = __ldg(ediv + e);
    float4 v = *(const float4*)(g_Wh + ((size_t)dv * N_NODES + s) * OUT_F + c * 4);
    float* q = out + (size_t)dd * OUT_TOT + dv * OUT_F + c * 4;
    asm volatile("red.global.add.v4.f32 [%0], {%1, %2, %3, %4};"
                 :: "l"(q), "f"(v.x), "f"(v.y), "f"(v.z), "f"(v.w) : "memory");
}

// ---------------------------------------------------------------------------
// Kernel 5: out = relu(out * norm[dst])  in-place
// ---------------------------------------------------------------------------
__global__ void k_finalize(float* __restrict__ out, const float* __restrict__ norm) {
    int i = blockIdx.x * blockDim.x + threadIdx.x;       // float4 index
    const int n4 = N_NODES * (OUT_TOT / 4);              // 14,400,000
    if (i >= n4) return;
    int n = i / (OUT_TOT / 4);
    float s = __ldg(norm + n);
    float4 v = ((float4*)out)[i];
    v.x = fmaxf(v.x * s, 0.f);
    v.y = fmaxf(v.y * s, 0.f);
    v.z = fmaxf(v.z * s, 0.f);
    v.w = fmaxf(v.w * s, 0.f);
    ((float4*)out)[i] = v;
}

// ---------------------------------------------------------------------------
extern "C" void kernel_launch(void* const* d_in, const int* in_sizes, int n_in,
                              void* d_out, int out_size) {
    const float* feature = (const float*)d_in[0];
    const float* norm    = (const float*)d_in[1];
    const float* W       = (const float*)d_in[2];
    const int*   src     = (const int*)d_in[3];
    const int*   dst     = (const int*)d_in[4];
    const int*   ediv    = (const int*)d_in[5];
    float* out = (float*)d_out;

    // 64KB dynamic smem for the GEMM tiles (idempotent; host-side, not captured)
    cudaFuncSetAttribute(k_gemm, cudaFuncAttributeMaxDynamicSharedMemorySize, 65536);

    k_transpose_W<<<(N_DIV * IN_F * OUT_F + 255) / 256, 256>>>(W);

    dim3 tg(NPAD / 32, IN_F / 32);
    k_transpose_feat<<<tg, dim3(32, 8)>>>(feature);

    int n4 = out_size / 4;
    k_zero<<<(n4 + 255) / 256, 256>>>((float4*)out, n4);

    dim3 gg((N_NODES + 63) / 64, N_DIV);
    k_gemm<<<gg, 256, 65536>>>(norm);

    long long st = (long long)N_EDGES * 16;
    k_scatter<<<(unsigned)((st + 255) / 256), 256>>>(src, dst, ediv, out);

    k_finalize<<<(n4 + 255) / 256, 256>>>(out, norm);
}

// round 2
// speedup vs baseline: 1.0564x; 1.0564x over previous
#include <cuda_runtime.h>

#define N_NODES 100000
#define NPAD    100096          // padded node count: multiple of 128 (GEMM node tile)
#define N_EDGES 1600000
#define N_DIV   9
#define D_PAD   10              // padded division count (division 9 = statically zero)
#define IN_F    128
#define OUT_F   64
#define OUT_TOT (N_DIV * OUT_F) // 576

// Scratch (device globals: allocation-free per harness rules; zero-initialized at load)
__device__ float g_Wh[(size_t)D_PAD * NPAD * OUT_F];     // 256 MB: projected + norm-scaled features
__device__ float g_featT[(size_t)IN_F * NPAD];           // 51.2 MB: feature^T * norm, [f][n]
__device__ float g_Wt[D_PAD * IN_F * OUT_F];             // 320 KB: W^T [d][f][o]; d=9 stays zero

// ---------------------------------------------------------------------------
// Kernel 0: transpose W [d][o][f] -> Wt [d][f][o]
// ---------------------------------------------------------------------------
__global__ void k_transpose_W(const float* __restrict__ W) {
    int t = blockIdx.x * blockDim.x + threadIdx.x;
    if (t >= N_DIV * IN_F * OUT_F) return;
    int o = t & (OUT_F - 1);
    int f = (t >> 6) & (IN_F - 1);
    int d = t >> 13;
    g_Wt[t] = W[d * IN_F * OUT_F + o * IN_F + f];
}

// ---------------------------------------------------------------------------
// Kernel 1: featT[f][n] = feature[n][f] * norm[n]   (norm folded in here)
// Zero-fills the NPAD tail so the GEMM needs no bounds checks on loads.
// ---------------------------------------------------------------------------
__global__ void k_transpose_feat(const float* __restrict__ feat,
                                 const float* __restrict__ norm) {
    __shared__ float tile[32][33];
    int n0 = blockIdx.x * 32;
    int f0 = blockIdx.y * 32;
    int x = threadIdx.x, y = threadIdx.y;  // 32 x 8
#pragma unroll
    for (int j = 0; j < 32; j += 8) {
        int n = n0 + y + j;
        tile[y + j][x] = (n < N_NODES) ? feat[(size_t)n * IN_F + f0 + x] * __ldg(norm + n)
                                       : 0.f;
    }
    __syncthreads();
#pragma unroll
    for (int j = 0; j < 32; j += 8) {
        g_featT[(size_t)(f0 + y + j) * NPAD + n0 + x] = tile[x][y + j];
    }
}

// ---------------------------------------------------------------------------
// Kernel 2: zero d_out (accumulator target for the edge scatter)
// ---------------------------------------------------------------------------
__global__ void k_zero(float4* __restrict__ out, int n4) {
    int i = blockIdx.x * blockDim.x + threadIdx.x;
    if (i < n4) out[i] = make_float4(0.f, 0.f, 0.f, 0.f);
}

// ---------------------------------------------------------------------------
// Kernel 3: GEMM  Wh[d][n][o] = featT[:,n] . Wt[d][:,o]
// CTA tile: 128 nodes x 128 outputs (= 2 divisions), K=128 resident in smem.
// Thread tile: 8 nodes x 8 outputs as split quads:
//   nodes  {ty*4..ty*4+3} U {64+ty*4..+3},  outputs {tx*4..+3} U {64+tx*4..+3}
// -> A loads are 2-address broadcasts, B loads are contiguous 256B per warp:
//    conflict-free smem, 64 MACs per 4 LDS.128.
// Inner math: packed fp32x2 FMA (exact fp32, 2 MACs/inst).
// ---------------------------------------------------------------------------
__device__ __forceinline__ void ffma2(unsigned long long& acc,
                                      unsigned long long a, unsigned long long b) {
    asm("fma.rn.f32x2 %0, %1, %2, %0;" : "+l"(acc) : "l"(a), "l"(b));
}
__device__ __forceinline__ unsigned long long dup2(float v) {
    unsigned long long r;
    asm("mov.b64 %0, {%1, %1};" : "=l"(r) : "f"(v));
    return r;
}

__global__ __launch_bounds__(256) void k_gemm() {
    extern __shared__ float sh[];
    float* AsT = sh;                   // [128][128]  AsT[k][m] = featT[k][n0+m]
    float* BsT = sh + IN_F * 128;      // [128][128]  cols 0-63: div d0, 64-127: div d0+1

    const int d0  = blockIdx.x * 2;    // gridDim.x = 5 -> d0 in {0,2,4,6,8}; d0+1==9 is zero
    const int n0  = blockIdx.y * 128;
    const int tid = threadIdx.x;

    // cooperative load: 2 * 16384 floats = 8192 float4, 32 per thread
#pragma unroll
    for (int it = 0; it < 16; it++) {
        int idx = tid + it * 256;            // 0..4095 float4 units
        int k = idx >> 5;
        int c = idx & 31;                    // float4 column within the 128-wide row
        ((float4*)AsT)[idx] =
            *(const float4*)(g_featT + (size_t)k * NPAD + n0 + c * 4);
        int dd = d0 + (c >> 4);
        int o  = (c & 15) * 4;
        ((float4*)BsT)[idx] =
            *(const float4*)(g_Wt + (dd * IN_F + k) * OUT_F + o);
    }
    __syncthreads();

    const int tx = tid & 15;   // output quads: tx*4 and 64+tx*4
    const int ty = tid >> 4;   // node quads:   ty*4 and 64+ty*4

    unsigned long long acc[4][8] = {};  // [node-pair][output] packed f32x2

#pragma unroll 4
    for (int k = 0; k < IN_F; k++) {
        const float* ar = AsT + k * 128 + ty * 4;
        ulonglong2 a01 = *(const ulonglong2*)ar;          // node pairs 0,1
        ulonglong2 a23 = *(const ulonglong2*)(ar + 64);   // node pairs 2,3
        const float* br = BsT + k * 128 + tx * 4;
        float4 b0 = *(const float4*)br;                   // div d0 outputs
        float4 b1 = *(const float4*)(br + 64);            // div d0+1 outputs

        unsigned long long bb;
        bb = dup2(b0.x); ffma2(acc[0][0], a01.x, bb); ffma2(acc[1][0], a01.y, bb);
                         ffma2(acc[2][0], a23.x, bb); ffma2(acc[3][0], a23.y, bb);
        bb = dup2(b0.y); ffma2(acc[0][1], a01.x, bb); ffma2(acc[1][1], a01.y, bb);
                         ffma2(acc[2][1], a23.x, bb); ffma2(acc[3][1], a23.y, bb);
        bb = dup2(b0.z); ffma2(acc[0][2], a01.x, bb); ffma2(acc[1][2], a01.y, bb);
                         ffma2(acc[2][2], a23.x, bb); ffma2(acc[3][2], a23.y, bb);
        bb = dup2(b0.w); ffma2(acc[0][3], a01.x, bb); ffma2(acc[1][3], a01.y, bb);
                         ffma2(acc[2][3], a23.x, bb); ffma2(acc[3][3], a23.y, bb);
        bb = dup2(b1.x); ffma2(acc[0][4], a01.x, bb); ffma2(acc[1][4], a01.y, bb);
                         ffma2(acc[2][4], a23.x, bb); ffma2(acc[3][4], a23.y, bb);
        bb = dup2(b1.y); ffma2(acc[0][5], a01.x, bb); ffma2(acc[1][5], a01.y, bb);
                         ffma2(acc[2][5], a23.x, bb); ffma2(acc[3][5], a23.y, bb);
        bb = dup2(b1.z); ffma2(acc[0][6], a01.x, bb); ffma2(acc[1][6], a01.y, bb);
                         ffma2(acc[2][6], a23.x, bb); ffma2(acc[3][6], a23.y, bb);
        bb = dup2(b1.w); ffma2(acc[0][7], a01.x, bb); ffma2(acc[1][7], a01.y, bb);
                         ffma2(acc[2][7], a23.x, bb); ffma2(acc[3][7], a23.y, bb);
    }

    // writeout: per node-pair p, halves are the two nodes; norm already folded in
#pragma unroll
    for (int p = 0; p < 4; p++) {
        float lo[8], hi[8];
#pragma unroll
        for (int o = 0; o < 8; o++)
            asm("mov.b64 {%0, %1}, %2;" : "=f"(lo[o]), "=f"(hi[o]) : "l"(acc[p][o]));
        int nb = n0 + ((p < 2) ? (ty * 4 + p * 2) : (64 + ty * 4 + (p - 2) * 2));
        if (nb < N_NODES) {
            *(float4*)(g_Wh + ((size_t)d0 * NPAD + nb) * OUT_F + tx * 4) =
                make_float4(lo[0], lo[1], lo[2], lo[3]);
            *(float4*)(g_Wh + ((size_t)(d0 + 1) * NPAD + nb) * OUT_F + tx * 4) =
                make_float4(lo[4], lo[5], lo[6], lo[7]);
        }
        if (nb + 1 < N_NODES) {
            *(float4*)(g_Wh + ((size_t)d0 * NPAD + nb + 1) * OUT_F + tx * 4) =
                make_float4(hi[0], hi[1], hi[2], hi[3]);
            *(float4*)(g_Wh + ((size_t)(d0 + 1) * NPAD + nb + 1) * OUT_F + tx * 4) =
                make_float4(hi[4], hi[5], hi[6], hi[7]);
        }
    }
}

// ---------------------------------------------------------------------------
// Kernel 4: edge scatter. 16 threads per edge, one float4 each.
// Vectorized no-return atomic (red.global.add.v4.f32).
// ---------------------------------------------------------------------------
__global__ __launch_bounds__(256) void k_scatter(const int* __restrict__ src,
                                                 const int* __restrict__ dst,
                                                 const int* __restrict__ ediv,
                                                 float* __restrict__ out) {
    int t = blockIdx.x * blockDim.x + threadIdx.x;
    int e = t >> 4;
    if (e >= N_EDGES) return;
    int c  = t & 15;
    int s  = __ldg(src + e);
    int dd = __ldg(dst + e);
    int dv = __ldg(ediv + e);
    float4 v = *(const float4*)(g_Wh + ((size_t)dv * NPAD + s) * OUT_F + c * 4);
    float* q = out + (size_t)dd * OUT_TOT + dv * OUT_F + c * 4;
    asm volatile("red.global.add.v4.f32 [%0], {%1, %2, %3, %4};"
                 :: "l"(q), "f"(v.x), "f"(v.y), "f"(v.z), "f"(v.w) : "memory");
}

// ---------------------------------------------------------------------------
// Kernel 5: out = relu(out * norm[dst])  in-place
// ---------------------------------------------------------------------------
__global__ void k_finalize(float* __restrict__ out, const float* __restrict__ norm) {
    int i = blockIdx.x * blockDim.x + threadIdx.x;       // float4 index
    const int n4 = N_NODES * (OUT_TOT / 4);
    if (i >= n4) return;
    int n = i / (OUT_TOT / 4);
    float s = __ldg(norm + n);
    float4 v = ((float4*)out)[i];
    v.x = fmaxf(v.x * s, 0.f);
    v.y = fmaxf(v.y * s, 0.f);
    v.z = fmaxf(v.z * s, 0.f);
    v.w = fmaxf(v.w * s, 0.f);
    ((float4*)out)[i] = v;
}

// ---------------------------------------------------------------------------
extern "C" void kernel_launch(void* const* d_in, const int* in_sizes, int n_in,
                              void* d_out, int out_size) {
    const float* feature = (const float*)d_in[0];
    const float* norm    = (const float*)d_in[1];
    const float* W       = (const float*)d_in[2];
    const int*   src     = (const int*)d_in[3];
    const int*   dst     = (const int*)d_in[4];
    const int*   ediv    = (const int*)d_in[5];
    float* out = (float*)d_out;

    cudaFuncSetAttribute(k_gemm, cudaFuncAttributeMaxDynamicSharedMemorySize, 131072);

    k_transpose_W<<<(N_DIV * IN_F * OUT_F + 255) / 256, 256>>>(W);

    dim3 tg(NPAD / 32, IN_F / 32);
    k_transpose_feat<<<tg, dim3(32, 8)>>>(feature, norm);

    int n4 = out_size / 4;
    k_zero<<<(n4 + 255) / 256, 256>>>((float4*)out, n4);

    // x = division pair (fast-varying) so consecutive CTAs share the A tile in L2
    dim3 gg(D_PAD / 2, NPAD / 128);
    k_gemm<<<gg, 256, 131072>>>();

    long long st = (long long)N_EDGES * 16;
    k_scatter<<<(unsigned)((st + 255) / 256), 256>>>(src, dst, ediv, out);

    k_finalize<<<(n4 + 255) / 256, 256>>>(out, norm);
}

// round 3
// speedup vs baseline: 1.4349x; 1.3583x over previous
#include <cuda_runtime.h>

#define N_NODES 100000
#define NPAD    100096          // padded node count: multiple of 128 (GEMM node tile)
#define N_EDGES 1600000
#define N_DIV   9
#define D_PAD   10              // padded division count (division 9 = statically zero)
#define IN_F    128
#define OUT_F   64
#define OUT_TOT (N_DIV * OUT_F) // 576

#define SCAN_BLK   1024
#define SCAN_NB    ((N_NODES + SCAN_BLK - 1) / SCAN_BLK)   // 98

// Scratch (device globals: allocation-free per harness rules)
__device__ float g_Wh[(size_t)D_PAD * NPAD * OUT_F];     // 256 MB projected feats
__device__ float g_featT[(size_t)IN_F * NPAD];           // 51.2 MB feature^T * norm
__device__ float g_Wt[D_PAD * IN_F * OUT_F];             // W^T [d][f][o]; d=9 stays zero
__device__ int   g_cnt[N_NODES];                         // histogram / fill cursor
__device__ int   g_rowptr[N_NODES + 1];                  // CSR row pointers (by dst)
__device__ int   g_bsum[128];                            // scan block sums
__device__ int   g_erec[N_EDGES];                        // packed src | (div<<17)

// ---------------------------------------------------------------------------
// Kernel 0: transpose W [d][o][f] -> Wt [d][f][o]
// ---------------------------------------------------------------------------
__global__ void k_transpose_W(const float* __restrict__ W) {
    int t = blockIdx.x * blockDim.x + threadIdx.x;
    if (t >= N_DIV * IN_F * OUT_F) return;
    int o = t & (OUT_F - 1);
    int f = (t >> 6) & (IN_F - 1);
    int d = t >> 13;
    g_Wt[t] = W[d * IN_F * OUT_F + o * IN_F + f];
}

// ---------------------------------------------------------------------------
// Kernel 1: featT[f][n] = feature[n][f] * norm[n]   (src norm folded in)
// ---------------------------------------------------------------------------
__global__ void k_transpose_feat(const float* __restrict__ feat,
                                 const float* __restrict__ norm) {
    __shared__ float tile[32][33];
    int n0 = blockIdx.x * 32;
    int f0 = blockIdx.y * 32;
    int x = threadIdx.x, y = threadIdx.y;  // 32 x 8
#pragma unroll
    for (int j = 0; j < 32; j += 8) {
        int n = n0 + y + j;
        tile[y + j][x] = (n < N_NODES) ? feat[(size_t)n * IN_F + f0 + x] * __ldg(norm + n)
                                       : 0.f;
    }
    __syncthreads();
#pragma unroll
    for (int j = 0; j < 32; j += 8) {
        g_featT[(size_t)(f0 + y + j) * NPAD + n0 + x] = tile[x][y + j];
    }
}

// ---------------------------------------------------------------------------
// CSR build: zero counts -> histogram -> scan(3) -> fill
// ---------------------------------------------------------------------------
__global__ void k_zero_cnt() {
    int i = blockIdx.x * blockDim.x + threadIdx.x;
    if (i < N_NODES) g_cnt[i] = 0;
}

__global__ void k_hist(const int* __restrict__ dst) {
    int e = blockIdx.x * blockDim.x + threadIdx.x;
    if (e < N_EDGES) atomicAdd(&g_cnt[dst[e]], 1);
}

__global__ __launch_bounds__(SCAN_BLK) void k_scan1() {
    __shared__ int s[SCAN_BLK];
    int tid = threadIdx.x;
    int i = blockIdx.x * SCAN_BLK + tid;
    int v = (i < N_NODES) ? g_cnt[i] : 0;
    s[tid] = v;
    __syncthreads();
#pragma unroll
    for (int off = 1; off < SCAN_BLK; off <<= 1) {
        int t = (tid >= off) ? s[tid - off] : 0;
        __syncthreads();
        s[tid] += t;
        __syncthreads();
    }
    if (i < N_NODES) g_rowptr[i] = s[tid] - v;   // exclusive (block-local)
    if (tid == SCAN_BLK - 1) g_bsum[blockIdx.x] = s[tid];
}

__global__ void k_scan2() {   // one block of 128, scans <=128 block sums
    __shared__ int s[128];
    int tid = threadIdx.x;
    int v = (tid < SCAN_NB) ? g_bsum[tid] : 0;
    s[tid] = v;
    __syncthreads();
#pragma unroll
    for (int off = 1; off < 128; off <<= 1) {
        int t = (tid >= off) ? s[tid - off] : 0;
        __syncthreads();
        s[tid] += t;
        __syncthreads();
    }
    g_bsum[tid] = s[tid] - v;  // exclusive
}

__global__ void k_scan3() {
    int i = blockIdx.x * blockDim.x + threadIdx.x;
    if (i < N_NODES) {
        g_rowptr[i] += g_bsum[i >> 10];
        g_cnt[i] = 0;                       // reuse as fill cursor
    }
    if (i == 0) g_rowptr[N_NODES] = N_EDGES;
}

__global__ void k_fill(const int* __restrict__ src, const int* __restrict__ dst,
                       const int* __restrict__ ediv) {
    int e = blockIdx.x * blockDim.x + threadIdx.x;
    if (e >= N_EDGES) return;
    int d = dst[e];
    int pos = g_rowptr[d] + atomicAdd(&g_cnt[d], 1);
    g_erec[pos] = src[e] | (ediv[e] << 17);
}

// ---------------------------------------------------------------------------
// Kernel 3: GEMM  Wh[d][n][o] = featT[:,n] . Wt[d][:,o]
// CTA tile: 128 nodes x 128 outputs (2 divisions). K split in 2x64 chunks,
// single-buffered -> 64KB smem -> 2 CTAs/SM (occ 25%, was 12.3%).
// Thread tile: 8 nodes x 8 outputs as split quads. Packed fp32x2 FMA.
// ---------------------------------------------------------------------------
__device__ __forceinline__ void ffma2(unsigned long long& acc,
                                      unsigned long long a, unsigned long long b) {
    asm("fma.rn.f32x2 %0, %1, %2, %0;" : "+l"(acc) : "l"(a), "l"(b));
}
__device__ __forceinline__ unsigned long long dup2(float v) {
    unsigned long long r;
    asm("mov.b64 %0, {%1, %1};" : "=l"(r) : "f"(v));
    return r;
}

__global__ __launch_bounds__(256, 2) void k_gemm() {
    __shared__ float AsT[64 * 128];   // AsT[k][m] = featT[kc*64+k][n0+m]
    __shared__ float BsT[64 * 128];   // cols 0-63: div d0, 64-127: div d0+1

    const int d0  = blockIdx.x * 2;
    const int n0  = blockIdx.y * 128;
    const int tid = threadIdx.x;
    const int tx  = tid & 15;
    const int ty  = tid >> 4;

    unsigned long long acc[4][8] = {};

#pragma unroll
    for (int kc = 0; kc < 2; kc++) {
        // load chunk: 2048 float4 each side, 8 per thread
#pragma unroll
        for (int it = 0; it < 8; it++) {
            int idx = tid + it * 256;        // 0..2047
            int k = idx >> 5;                // 0..63
            int c = idx & 31;
            ((float4*)AsT)[idx] =
                *(const float4*)(g_featT + (size_t)(kc * 64 + k) * NPAD + n0 + c * 4);
            int dd = d0 + (c >> 4);
            int o  = (c & 15) * 4;
            ((float4*)BsT)[idx] =
                *(const float4*)(g_Wt + (dd * IN_F + kc * 64 + k) * OUT_F + o);
        }
        __syncthreads();

#pragma unroll 4
        for (int k = 0; k < 64; k++) {
            const float* ar = AsT + k * 128 + ty * 4;
            ulonglong2 a01 = *(const ulonglong2*)ar;
            ulonglong2 a23 = *(const ulonglong2*)(ar + 64);
            const float* br = BsT + k * 128 + tx * 4;
            float4 b0 = *(const float4*)br;
            float4 b1 = *(const float4*)(br + 64);

            unsigned long long bb;
            bb = dup2(b0.x); ffma2(acc[0][0], a01.x, bb); ffma2(acc[1][0], a01.y, bb);
                             ffma2(acc[2][0], a23.x, bb); ffma2(acc[3][0], a23.y, bb);
            bb = dup2(b0.y); ffma2(acc[0][1], a01.x, bb); ffma2(acc[1][1], a01.y, bb);
                             ffma2(acc[2][1], a23.x, bb); ffma2(acc[3][1], a23.y, bb);
            bb = dup2(b0.z); ffma2(acc[0][2], a01.x, bb); ffma2(acc[1][2], a01.y, bb);
                             ffma2(acc[2][2], a23.x, bb); ffma2(acc[3][2], a23.y, bb);
            bb = dup2(b0.w); ffma2(acc[0][3], a01.x, bb); ffma2(acc[1][3], a01.y, bb);
                             ffma2(acc[2][3], a23.x, bb); ffma2(acc[3][3], a23.y, bb);
            bb = dup2(b1.x); ffma2(acc[0][4], a01.x, bb); ffma2(acc[1][4], a01.y, bb);
                             ffma2(acc[2][4], a23.x, bb); ffma2(acc[3][4], a23.y, bb);
            bb = dup2(b1.y); ffma2(acc[0][5], a01.x, bb); ffma2(acc[1][5], a01.y, bb);
                             ffma2(acc[2][5], a23.x, bb); ffma2(acc[3][5], a23.y, bb);
            bb = dup2(b1.z); ffma2(acc[0][6], a01.x, bb); ffma2(acc[1][6], a01.y, bb);
                             ffma2(acc[2][6], a23.x, bb); ffma2(acc[3][6], a23.y, bb);
            bb = dup2(b1.w); ffma2(acc[0][7], a01.x, bb); ffma2(acc[1][7], a01.y, bb);
                             ffma2(acc[2][7], a23.x, bb); ffma2(acc[3][7], a23.y, bb);
        }
        __syncthreads();
    }

#pragma unroll
    for (int p = 0; p < 4; p++) {
        float lo[8], hi[8];
#pragma unroll
        for (int o = 0; o < 8; o++)
            asm("mov.b64 {%0, %1}, %2;" : "=f"(lo[o]), "=f"(hi[o]) : "l"(acc[p][o]));
        int nb = n0 + ((p < 2) ? (ty * 4 + p * 2) : (64 + ty * 4 + (p - 2) * 2));
        *(float4*)(g_Wh + ((size_t)d0 * NPAD + nb) * OUT_F + tx * 4) =
            make_float4(lo[0], lo[1], lo[2], lo[3]);
        *(float4*)(g_Wh + ((size_t)(d0 + 1) * NPAD + nb) * OUT_F + tx * 4) =
            make_float4(lo[4], lo[5], lo[6], lo[7]);
        *(float4*)(g_Wh + ((size_t)d0 * NPAD + nb + 1) * OUT_F + tx * 4) =
            make_float4(hi[0], hi[1], hi[2], hi[3]);
        *(float4*)(g_Wh + ((size_t)(d0 + 1) * NPAD + nb + 1) * OUT_F + tx * 4) =
            make_float4(hi[4], hi[5], hi[6], hi[7]);
    }
}

// ---------------------------------------------------------------------------
// Kernel 4: pull-mode aggregation. One warp per dst node.
// Accumulates all incoming messages into a 576-float smem row, then writes
// out = relu(acc * norm[n]) exactly once. No zero pass, no global atomics,
// no finalize pass.
// ---------------------------------------------------------------------------
#define PULL_WARPS 8
__global__ __launch_bounds__(256) void k_pull(const float* __restrict__ norm,
                                              float* __restrict__ out) {
    __shared__ float acc[PULL_WARPS][OUT_TOT];   // 18 KB
    int w = threadIdx.x >> 5, lane = threadIdx.x & 31;
    int n = blockIdx.x * PULL_WARPS + w;
    if (n >= N_NODES) return;                    // uniform per warp
    float* a = acc[w];
#pragma unroll
    for (int j = lane; j < OUT_TOT; j += 32) a[j] = 0.f;
    __syncwarp();

    int beg = g_rowptr[n], end = g_rowptr[n + 1];
    int i = beg;
    // 2-way unrolled: two independent gathers in flight per warp
    for (; i + 1 < end; i += 2) {
        int r0 = __ldg(g_erec + i);
        int r1 = __ldg(g_erec + i + 1);
        int s0 = r0 & 0x1FFFF, v0 = r0 >> 17;
        int s1 = r1 & 0x1FFFF, v1 = r1 >> 17;
        float2 m0 = __ldg((const float2*)(g_Wh + ((size_t)v0 * NPAD + s0) * OUT_F) + lane);
        float2 m1 = __ldg((const float2*)(g_Wh + ((size_t)v1 * NPAD + s1) * OUT_F) + lane);
        float* p0 = a + v0 * OUT_F + lane * 2;
        p0[0] += m0.x; p0[1] += m0.y;
        float* p1 = a + v1 * OUT_F + lane * 2;
        p1[0] += m1.x; p1[1] += m1.y;
    }
    if (i < end) {
        int r0 = __ldg(g_erec + i);
        int s0 = r0 & 0x1FFFF, v0 = r0 >> 17;
        float2 m0 = __ldg((const float2*)(g_Wh + ((size_t)v0 * NPAD + s0) * OUT_F) + lane);
        float* p0 = a + v0 * OUT_F + lane * 2;
        p0[0] += m0.x; p0[1] += m0.y;
    }
    __syncwarp();

    float sc = __ldg(norm + n);
    float4* o4 = (float4*)(out + (size_t)n * OUT_TOT);
    const float4* a4 = (const float4*)a;
#pragma unroll
    for (int j = lane; j < OUT_TOT / 4; j += 32) {
        float4 v = a4[j];
        v.x = fmaxf(v.x * sc, 0.f);
        v.y = fmaxf(v.y * sc, 0.f);
        v.z = fmaxf(v.z * sc, 0.f);
        v.w = fmaxf(v.w * sc, 0.f);
        o4[j] = v;
    }
}

// ---------------------------------------------------------------------------
extern "C" void kernel_launch(void* const* d_in, const int* in_sizes, int n_in,
                              void* d_out, int out_size) {
    const float* feature = (const float*)d_in[0];
    const float* norm    = (const float*)d_in[1];
    const float* W       = (const float*)d_in[2];
    const int*   src     = (const int*)d_in[3];
    const int*   dst     = (const int*)d_in[4];
    const int*   ediv    = (const int*)d_in[5];
    float* out = (float*)d_out;

    // CSR build (independent of GEMM chain)
    k_zero_cnt<<<(N_NODES + 255) / 256, 256>>>();
    k_hist<<<(N_EDGES + 255) / 256, 256>>>(dst);
    k_scan1<<<SCAN_NB, SCAN_BLK>>>();
    k_scan2<<<1, 128>>>();
    k_scan3<<<(N_NODES + 255) / 256, 256>>>();
    k_fill<<<(N_EDGES + 255) / 256, 256>>>(src, dst, ediv);

    // Projection chain
    k_transpose_W<<<(N_DIV * IN_F * OUT_F + 255) / 256, 256>>>(W);
    dim3 tg(NPAD / 32, IN_F / 32);
    k_transpose_feat<<<tg, dim3(32, 8)>>>(feature, norm);
    dim3 gg(D_PAD / 2, NPAD / 128);
    k_gemm<<<gg, 256>>>();

    // Pull + fused epilogue
    k_pull<<<N_NODES / PULL_WARPS, 256>>>(norm, out);
}

// round 9
// speedup vs baseline: 1.9260x; 1.3422x over previous
#include <cuda_runtime.h>
#include <cuda_bf16.h>
#include <cstdint>

#define N_NODES 100000
#define NPAD    100096          // multiple of 128
#define NT      (NPAD / 128)    // 782 node tiles
#define N_EDGES 1600000
#define N_DIV   9
#define IN_F    128
#define OUT_F   64
#define OUT_TOT (N_DIV * OUT_F) // 576

#define SCAN_BLK 1024
#define SCAN_NB  ((N_NODES + SCAN_BLK - 1) / SCAN_BLK)

#define A_FRAGS  (NT * 2048)    // [tile][tm 0..7][kk 0..7][lane 0..31]
#define B_FRAGS  (N_DIV * 2048) // [d][tn 0..7][kk 0..7][lane 0..31]

// ---------------- device scratch (no allocations allowed) -------------------
__device__ float g_Wh[(size_t)N_DIV * NPAD * OUT_F];   // 230 MB projected feats
__device__ uint4 g_Afrag[(size_t)A_FRAGS * 2];         // 51.2 MB: hi plane, then lo plane
__device__ uint2 g_Bfrag[B_FRAGS * 2];                 // 294 KB: hi plane, then lo plane
__device__ int   g_cnt[N_NODES];
__device__ int   g_rowptr[N_NODES + 1];
__device__ int   g_bsum[128];
__device__ int   g_erec[N_EDGES];                      // packed src | (div<<17)

// ---------------------------------------------------------------------------
// bf16 hi/lo split of a float2, packed as one .b32 per plane (low k in low 16)
// ---------------------------------------------------------------------------
__device__ __forceinline__ void split2(float2 v, uint32_t& h, uint32_t& l) {
    __nv_bfloat16 h0 = __float2bfloat16_rn(v.x);
    __nv_bfloat16 h1 = __float2bfloat16_rn(v.y);
    __nv_bfloat16 l0 = __float2bfloat16_rn(v.x - __bfloat162float(h0));
    __nv_bfloat16 l1 = __float2bfloat16_rn(v.y - __bfloat162float(h1));
    h = (uint32_t)__bfloat16_as_ushort(h0) | ((uint32_t)__bfloat16_as_ushort(h1) << 16);
    l = (uint32_t)__bfloat16_as_ushort(l0) | ((uint32_t)__bfloat16_as_ushort(l1) << 16);
}

// ---------------------------------------------------------------------------
// A-fragment conversion: feat[n][k]*norm[n] -> m16n8k16 A fragments (hi+lo).
// Fragment for (tile, tm, kk), lane: a0=A[r][2c,2c+1], a1=A[r+8][..],
// a2=A[r][2c+8,2c+9], a3=A[r+8][2c+8..]; r=lane>>2, c=lane&3.
// ---------------------------------------------------------------------------
__global__ void k_conv_feat(const float* __restrict__ feat,
                            const float* __restrict__ norm) {
    int t = blockIdx.x * 256 + threadIdx.x;
    if (t >= A_FRAGS) return;
    int lane = t & 31, kk = (t >> 5) & 7, tm = (t >> 8) & 7, tile = t >> 11;
    int r = lane >> 2, cc = lane & 3;
    int n0 = tile * 128 + tm * 16 + r;
    int n1 = n0 + 8;
    int k0 = kk * 16 + cc * 2;

    float2 f00 = make_float2(0.f, 0.f), f01 = f00, f10 = f00, f11 = f00;
    if (n0 < N_NODES) {
        float s = __ldg(norm + n0);
        float2 a = *(const float2*)(feat + (size_t)n0 * IN_F + k0);
        float2 b = *(const float2*)(feat + (size_t)n0 * IN_F + k0 + 8);
        f00 = make_float2(a.x * s, a.y * s);
        f01 = make_float2(b.x * s, b.y * s);
    }
    if (n1 < N_NODES) {
        float s = __ldg(norm + n1);
        float2 a = *(const float2*)(feat + (size_t)n1 * IN_F + k0);
        float2 b = *(const float2*)(feat + (size_t)n1 * IN_F + k0 + 8);
        f10 = make_float2(a.x * s, a.y * s);
        f11 = make_float2(b.x * s, b.y * s);
    }
    uint4 hi, lo;
    split2(f00, hi.x, lo.x);   // a0
    split2(f10, hi.y, lo.y);   // a1 (row+8)
    split2(f01, hi.z, lo.z);   // a2 (k+8)
    split2(f11, hi.w, lo.w);   // a3
    g_Afrag[t] = hi;
    g_Afrag[(size_t)A_FRAGS + t] = lo;
}

// ---------------------------------------------------------------------------
// B-fragment conversion: W[d][o][k] -> m16n8k16 B fragments (col-major B[k][n]).
// b0 = {B[2c][n], B[2c+1][n]}, b1 = {B[2c+8][n], B[2c+9][n]}; n = lane>>2.
// ---------------------------------------------------------------------------
__global__ void k_conv_W(const float* __restrict__ W) {
    int t = blockIdx.x * 256 + threadIdx.x;
    if (t >= B_FRAGS) return;
    int lane = t & 31, kk = (t >> 5) & 7, tn = (t >> 8) & 7, d = t >> 11;
    int n = tn * 8 + (lane >> 2);
    int k0 = kk * 16 + (lane & 3) * 2;
    const float* p = W + ((size_t)d * OUT_F + n) * IN_F;
    float2 v0 = make_float2(__ldg(p + k0), __ldg(p + k0 + 1));
    float2 v1 = make_float2(__ldg(p + k0 + 8), __ldg(p + k0 + 9));
    uint2 hi, lo;
    split2(v0, hi.x, lo.x);
    split2(v1, hi.y, lo.y);
    g_Bfrag[t] = hi;
    g_Bfrag[B_FRAGS + t] = lo;
}

// ---------------------------------------------------------------------------
// CSR build: zero -> histogram -> 3-phase scan -> fill
// ---------------------------------------------------------------------------
__global__ void k_zero_cnt() {
    int i = blockIdx.x * blockDim.x + threadIdx.x;
    if (i < N_NODES) g_cnt[i] = 0;
}
__global__ void k_hist(const int* __restrict__ dst) {
    int e = blockIdx.x * blockDim.x + threadIdx.x;
    if (e < N_EDGES) atomicAdd(&g_cnt[dst[e]], 1);
}
__global__ __launch_bounds__(SCAN_BLK) void k_scan1() {
    __shared__ int s[SCAN_BLK];
    int tid = threadIdx.x;
    int i = blockIdx.x * SCAN_BLK + tid;
    int v = (i < N_NODES) ? g_cnt[i] : 0;
    s[tid] = v;
    __syncthreads();
#pragma unroll
    for (int off = 1; off < SCAN_BLK; off <<= 1) {
        int t = (tid >= off) ? s[tid - off] : 0;
        __syncthreads();
        s[tid] += t;
        __syncthreads();
    }
    if (i < N_NODES) g_rowptr[i] = s[tid] - v;
    if (tid == SCAN_BLK - 1) g_bsum[blockIdx.x] = s[tid];
}
__global__ void k_scan2() {
    __shared__ int s[128];
    int tid = threadIdx.x;
    int v = (tid < SCAN_NB) ? g_bsum[tid] : 0;
    s[tid] = v;
    __syncthreads();
#pragma unroll
    for (int off = 1; off < 128; off <<= 1) {
        int t = (tid >= off) ? s[tid - off] : 0;
        __syncthreads();
        s[tid] += t;
        __syncthreads();
    }
    g_bsum[tid] = s[tid] - v;
}
__global__ void k_scan3() {
    int i = blockIdx.x * blockDim.x + threadIdx.x;
    if (i < N_NODES) {
        g_rowptr[i] += g_bsum[i >> 10];
        g_cnt[i] = 0;
    }
    if (i == 0) g_rowptr[N_NODES] = N_EDGES;
}
__global__ void k_fill(const int* __restrict__ src, const int* __restrict__ dst,
                       const int* __restrict__ ediv) {
    int e = blockIdx.x * blockDim.x + threadIdx.x;
    if (e >= N_EDGES) return;
    int d = dst[e];
    int pos = g_rowptr[d] + atomicAdd(&g_cnt[d], 1);
    g_erec[pos] = src[e] | (ediv[e] << 17);
}

// ---------------------------------------------------------------------------
// HMMA helper: D(f32) += A(bf16) x B(bf16), m16n8k16
// ---------------------------------------------------------------------------
__device__ __forceinline__ void mma16816(float* c, const uint4& a, const uint2& b) {
    asm volatile(
        "mma.sync.aligned.m16n8k16.row.col.f32.bf16.bf16.f32 "
        "{%0,%1,%2,%3}, {%4,%5,%6,%7}, {%8,%9}, {%0,%1,%2,%3};"
        : "+f"(c[0]), "+f"(c[1]), "+f"(c[2]), "+f"(c[3])
        : "r"(a.x), "r"(a.y), "r"(a.z), "r"(a.w), "r"(b.x), "r"(b.y));
}

// ---------------------------------------------------------------------------
// Tensor-core GEMM: CTA = 128 nodes x 64 outs, loops 9 divisions.
// 8 warps in 4(m) x 2(n); warp tile 32x32 = 2 m-tiles x 4 n-tiles.
// bf16x3: D = Ah*Bh + Ah*Bl + Al*Bh. A fragments re-read from L1 per division.
// ---------------------------------------------------------------------------
__global__ __launch_bounds__(256, 2) void k_gemm_mma() {
    const int tile = blockIdx.x;
    const int tid = threadIdx.x, lane = tid & 31, warp = tid >> 5;
    const int wm = warp >> 1, wn = warp & 1;

    const uint4* Ah = g_Afrag;
    const uint4* Al = g_Afrag + (size_t)A_FRAGS;
    const uint2* Bh = g_Bfrag;
    const uint2* Bl = g_Bfrag + B_FRAGS;

    const size_t abase = (((size_t)tile * 8 + wm * 2) * 8) * 32 + lane; // + i*256 + kk*32

    for (int d = 0; d < N_DIV; d++) {
        float c[2][4][4] = {};
        const size_t bbase = (((size_t)d * 8 + wn * 4) * 8) * 32 + lane; // + j*256 + kk*32

#pragma unroll
        for (int kk = 0; kk < 8; kk++) {
            uint4 ah[2], al[2];
            uint2 bh[4], bl[4];
#pragma unroll
            for (int i = 0; i < 2; i++) {
                ah[i] = __ldg(Ah + abase + (size_t)i * 256 + kk * 32);
                al[i] = __ldg(Al + abase + (size_t)i * 256 + kk * 32);
            }
#pragma unroll
            for (int j = 0; j < 4; j++) {
                bh[j] = __ldg(Bh + bbase + (size_t)j * 256 + kk * 32);
                bl[j] = __ldg(Bl + bbase + (size_t)j * 256 + kk * 32);
            }
            // term-major ordering: 8 independent accumulator chains per term
#pragma unroll
            for (int i = 0; i < 2; i++)
#pragma unroll
                for (int j = 0; j < 4; j++) mma16816(c[i][j], ah[i], bh[j]);
#pragma unroll
            for (int i = 0; i < 2; i++)
#pragma unroll
                for (int j = 0; j < 4; j++) mma16816(c[i][j], ah[i], bl[j]);
#pragma unroll
            for (int i = 0; i < 2; i++)
#pragma unroll
                for (int j = 0; j < 4; j++) mma16816(c[i][j], al[i], bh[j]);
        }

        // epilogue: c0,c1 at (r, 2cc), c2,c3 at (r+8, 2cc)
        const int r = lane >> 2, cc = lane & 3;
#pragma unroll
        for (int i = 0; i < 2; i++) {
            int m0 = tile * 128 + wm * 32 + i * 16 + r;
#pragma unroll
            for (int j = 0; j < 4; j++) {
                int o = wn * 32 + j * 8 + cc * 2;
                if (m0 < N_NODES)
                    *(float2*)(g_Wh + ((size_t)d * NPAD + m0) * OUT_F + o) =
                        make_float2(c[i][j][0], c[i][j][1]);
                if (m0 + 8 < N_NODES)
                    *(float2*)(g_Wh + ((size_t)d * NPAD + m0 + 8) * OUT_F + o) =
                        make_float2(c[i][j][2], c[i][j][3]);
            }
        }
    }
}

// ---------------------------------------------------------------------------
// Pull-mode aggregation: one warp per dst node, smem accumulator, fused epilogue.
// ---------------------------------------------------------------------------
#define PULL_WARPS 8
__global__ __launch_bounds__(256) void k_pull(const float* __restrict__ norm,
                                              float* __restrict__ out) {
    __shared__ float acc[PULL_WARPS][OUT_TOT];
    int w = threadIdx.x >> 5, lane = threadIdx.x & 31;
    int n = blockIdx.x * PULL_WARPS + w;
    if (n >= N_NODES) return;
    float* a = acc[w];
#pragma unroll
    for (int j = lane; j < OUT_TOT; j += 32) a[j] = 0.f;
    __syncwarp();

    int beg = g_rowptr[n], end = g_rowptr[n + 1];
    int i = beg;
    for (; i + 1 < end; i += 2) {
        int r0 = __ldg(g_erec + i);
        int r1 = __ldg(g_erec + i + 1);
        int s0 = r0 & 0x1FFFF, v0 = r0 >> 17;
        int s1 = r1 & 0x1FFFF, v1 = r1 >> 17;
        float2 m0 = __ldg((const float2*)(g_Wh + ((size_t)v0 * NPAD + s0) * OUT_F) + lane);
        float2 m1 = __ldg((const float2*)(g_Wh + ((size_t)v1 * NPAD + s1) * OUT_F) + lane);
        float* p0 = a + v0 * OUT_F + lane * 2;
        p0[0] += m0.x; p0[1] += m0.y;
        float* p1 = a + v1 * OUT_F + lane * 2;
        p1[0] += m1.x; p1[1] += m1.y;
    }
    if (i < end) {
        int r0 = __ldg(g_erec + i);
        int s0 = r0 & 0x1FFFF, v0 = r0 >> 17;
        float2 m0 = __ldg((const float2*)(g_Wh + ((size_t)v0 * NPAD + s0) * OUT_F) + lane);
        float* p0 = a + v0 * OUT_F + lane * 2;
        p0[0] += m0.x; p0[1] += m0.y;
    }
    __syncwarp();

    float sc = __ldg(norm + n);
    float4* o4 = (float4*)(out + (size_t)n * OUT_TOT);
    const float4* a4 = (const float4*)a;
#pragma unroll
    for (int j = lane; j < OUT_TOT / 4; j += 32) {
        float4 v = a4[j];
        v.x = fmaxf(v.x * sc, 0.f);
        v.y = fmaxf(v.y * sc, 0.f);
        v.z = fmaxf(v.z * sc, 0.f);
        v.w = fmaxf(v.w * sc, 0.f);
        o4[j] = v;
    }
}

// ---------------------------------------------------------------------------
extern "C" void kernel_launch(void* const* d_in, const int* in_sizes, int n_in,
                              void* d_out, int out_size) {
    const float* feature = (const float*)d_in[0];
    const float* norm    = (const float*)d_in[1];
    const float* W       = (const float*)d_in[2];
    const int*   src     = (const int*)d_in[3];
    const int*   dst     = (const int*)d_in[4];
    const int*   ediv    = (const int*)d_in[5];
    float* out = (float*)d_out;

    // CSR build (independent chain)
    k_zero_cnt<<<(N_NODES + 255) / 256, 256>>>();
    k_hist<<<(N_EDGES + 255) / 256, 256>>>(dst);
    k_scan1<<<SCAN_NB, SCAN_BLK>>>();
    k_scan2<<<1, 128>>>();
    k_scan3<<<(N_NODES + 255) / 256, 256>>>();
    k_fill<<<(N_EDGES + 255) / 256, 256>>>(src, dst, ediv);

    // bf16x3 fragment prep + tensor-core (mma.sync) GEMM
    k_conv_W<<<(B_FRAGS + 255) / 256, 256>>>(W);
    k_conv_feat<<<(A_FRAGS + 255) / 256, 256>>>(feature, norm);
    k_gemm_mma<<<NT, 256>>>();

    // Pull + fused epilogue
    k_pull<<<N_NODES / PULL_WARPS, 256>>>(norm, out);
}